// round 11
// baseline (speedup 1.0000x reference)
#include <cuda_runtime.h>
#include <cuda_bf16.h>

// Problem constants (fixed by the reference: B=512, V=32768, C=16)
#define BB   512
#define VV   32768
#define CC   16
#define TPB  128               // 128 threads/block (v-tile width)
#define SPLIT 4                // 4 b-splits
#define BPS  (BB / SPLIT)      // 128 samples per split
#define VBLOCKS (VV / TPB)     // 256 v-tiles -> grid (256,4) = 1024 blocks

// Deterministic scratch: per-split partial sums [SPLIT][C][V] (8 MB).
__device__ float    g_partial[(size_t)SPLIT * CC * VV];
// Per-v-tile arrival counter. Never reset: survivor = (old % SPLIT == SPLIT-1),
// which is replay-safe under CUDA-graph re-execution.
__device__ unsigned g_arrive[VBLOCKS];

// ---------------------------------------------------------------------------
// Fused kernel: gather + |sv*w| + segment-sum; the last-arriving block per
// v-tile then finalizes that tile (split-reduce + count + init-decode + EMA),
// overlapping finalize traffic with other tiles' accumulation stragglers.
// Gather core byte-identical to the version measured DRAM-bound at ~87% of
// peak (~1.15 GB mandatory traffic; W_eff gather = 1 float per 64B burst).
// ---------------------------------------------------------------------------
__global__ __launch_bounds__(TPB) void fused_kernel(
    const float*         __restrict__ sv,
    const float*         __restrict__ W,
    const int*           __restrict__ labels,
    const float*         __restrict__ centroids,
    const unsigned char* __restrict__ initp,
    float*               __restrict__ out)
{
    __shared__ float acc[CC][TPB];
    __shared__ int   slab[BPS];

    const int tid   = threadIdx.x;
    const int v     = blockIdx.x * TPB + tid;
    const int split = blockIdx.y;
    const int b0    = split * BPS;

    slab[tid] = labels[b0 + tid];          // BPS == TPB == 128
#pragma unroll
    for (int c = 0; c < CC; ++c) acc[c][tid] = 0.0f;
    __syncthreads();

    const float* svp = sv + (size_t)b0 * VV + v;
    const float* Wp  = W  + ((size_t)b0 * VV + v) * CC;

    // 8 b's per batch: 16 independent global loads in flight per thread.
#pragma unroll 1
    for (int bb = 0; bb < BPS; bb += 8) {
        int   l[8];
        float s[8];
        float w[8];
#pragma unroll
        for (int k = 0; k < 8; ++k) l[k] = slab[bb + k];
#pragma unroll
        for (int k = 0; k < 8; ++k)
            s[k] = __ldcs(svp + (size_t)(bb + k) * VV);
#pragma unroll
        for (int k = 0; k < 8; ++k)
            w[k] = __ldcs(Wp + (size_t)(bb + k) * VV * CC + l[k]);
#pragma unroll
        for (int k = 0; k < 8; ++k)
            acc[l[k]][tid] += fabsf(s[k] * w[k]);
    }

    // Coalesced partial write (fully written -> no zeroing needed).
    float* outp = g_partial + ((size_t)split * CC) * VV + v;
#pragma unroll
    for (int c = 0; c < CC; ++c)
        outp[(size_t)c * VV] = acc[c][tid];

    // ---- arrival protocol (CUDA threadFenceReduction pattern) ----
    __threadfence();                       // partials visible before signal
    __shared__ unsigned s_old;
    __syncthreads();                       // all stores issued before tid0 signals
    if (tid == 0) s_old = atomicAdd(&g_arrive[blockIdx.x], 1u);
    __syncthreads();
    if (s_old % SPLIT != SPLIT - 1u) return;

    // =======================================================================
    // Survivor: finalize this v-tile (128 columns x 16 classes).
    // Deterministic: fixed reduction order, same gmem reads whichever block wins.
    // =======================================================================
    __shared__ int s_cnt[CC];
    __shared__ int s_ini[CC];
    __shared__ int s_mode;

    if (tid < CC) s_cnt[tid] = 0;
    __syncthreads();

    // Count all 512 labels (4 per thread, smem atomics).
    for (int b = tid; b < BB; b += TPB)
        atomicAdd(&s_cnt[labels[b]], 1);

    // Dtype sniff for `initialized` (numpy bool vs int32 vs float32).
    if (tid == 0) {
        const int4 i4 = *(const int4*)initp;           // first 16 bytes
        const unsigned char* bp = (const unsigned char*)&i4;
        bool i32like = true, f32like = true, anyNZ = false;
        for (int i = 0; i < 16; ++i) {
            if ((i & 3) != 0 && bp[i] != 0) i32like = false;
            if (bp[i] != 0) anyNZ = true;
        }
        const float* fp = (const float*)&i4;
        for (int k = 0; k < 4; ++k)
            if (!(fp[k] == 0.0f || fp[k] == 1.0f)) f32like = false;
        s_mode = !anyNZ ? 0 : (f32like ? 2 : (i32like ? 1 : 0));
    }
    __syncthreads();
    if (tid < CC) {
        int c = tid, ini;
        if (s_mode == 2)      ini = (((const float*)initp)[c] != 0.0f);
        else if (s_mode == 1) ini = (((const int*)initp)[c] != 0);
        else                  ini = (initp[c] != 0);
        s_ini[c] = ini;
    }
    __syncthreads();

    const float ALPHA = (float)(2.0 / 1001.0);  // 1 - MOMENTUM

    // 16 classes x 1 column per thread; process 4 classes per chunk so
    // 16 partial loads + 4 centroid loads are in flight together (L2-hot).
#pragma unroll
    for (int cb = 0; cb < CC; cb += 4) {
        float t[4][SPLIT];
        float ct[4];
#pragma unroll
        for (int j = 0; j < 4; ++j) {
            const int c = cb + j;
#pragma unroll
            for (int p = 0; p < SPLIT; ++p)
                t[j][p] = g_partial[((size_t)p * CC + c) * VV + v];
            ct[j] = centroids[(size_t)c * VV + v];
        }
#pragma unroll
        for (int j = 0; j < 4; ++j) {
            const int c = cb + j;
            float s = 0.0f;
#pragma unroll
            for (int p = 0; p < SPLIT; ++p) s += t[j][p];

            const int   cnt = s_cnt[c];
            const float m   = s / fmaxf((float)cnt, 1.0f);
            const float u   = s_ini[c] ? (ct[j] + ALPHA * (m - ct[j])) : m;
            out[(size_t)c * VV + v] = (cnt > 0) ? u : ct[j];
        }
    }
}

// ---------------------------------------------------------------------------
// Launch. Inputs bound by UNIQUE element count (robust to metadata order):
//   sparse_vector f32 [B,V]     -> 16,777,216
//   W_eff         f32 [B,V,C]   -> 268,435,456
//   labels        i32 [B]       -> 512
//   centroids     f32 [C,V]     -> 524,288
//   initialized   bool[C]       -> 16
// ---------------------------------------------------------------------------
extern "C" void kernel_launch(void* const* d_in, const int* in_sizes, int n_in,
                              void* d_out, int out_size)
{
    const float*         sv   = nullptr;
    const float*         W    = nullptr;
    const int*           lab  = nullptr;
    const float*         cent = nullptr;
    const unsigned char* init = nullptr;

    for (int i = 0; i < n_in; ++i) {
        long n = (long)in_sizes[i];
        if      (n == (long)BB * VV)       sv   = (const float*)d_in[i];
        else if (n == (long)BB * VV * CC)  W    = (const float*)d_in[i];
        else if (n == (long)BB)            lab  = (const int*)d_in[i];
        else if (n == (long)CC * VV)       cent = (const float*)d_in[i];
        else if (n == (long)CC)            init = (const unsigned char*)d_in[i];
    }
    if (!sv)   sv   = (const float*)d_in[0];
    if (!W)    W    = (const float*)d_in[1];
    if (!lab)  lab  = (const int*)d_in[2];
    if (!cent) cent = (const float*)d_in[3];
    if (!init) init = (const unsigned char*)d_in[4];

    float* out = (float*)d_out;

    fused_kernel<<<dim3(VBLOCKS, SPLIT), TPB>>>(sv, W, lab, cent, init, out);
}

// round 14
// speedup vs baseline: 1.0021x; 1.0021x over previous
#include <cuda_runtime.h>
#include <cuda_bf16.h>

// Problem constants (fixed by the reference: B=512, V=32768, C=16)
#define BB   512
#define VV   32768
#define CC   16
#define TPB  256
#define SPLIT 8
#define BPS  (BB / SPLIT)      // 64 samples per split
#define VBLOCKS (VV / TPB)     // 128 v-tiles -> grid (128,8) = 1024 blocks

// Deterministic scratch: per-split partial sums [SPLIT][C][V] (16 MB).
__device__ float g_partial[(size_t)SPLIT * CC * VV];

// ---------------------------------------------------------------------------
// Kernel 1: gather + |sv*w| + segment-sum into per-split partials.
// Grid (VBLOCKS, SPLIT); each thread owns one v column for 64 b's,
// accumulating in smem[class][tid] (same class across warp -> broadcast LDS
// + conflict-free STS). MEASURED: DRAM-bound at 87.3% of peak, 6.92 TB/s,
// against a ~1.15 GB mandatory-traffic floor (W_eff gather = 1 float per
// 64B burst, irreducible). Fusion (R11) and SPLIT=4 (R10) both measured
// worse. FROZEN.
// ---------------------------------------------------------------------------
__global__ __launch_bounds__(TPB) void accum_kernel(
    const float* __restrict__ sv,
    const float* __restrict__ W,
    const int*   __restrict__ labels)
{
    __shared__ float acc[CC][TPB];
    __shared__ int   slab[BPS];

    const int tid   = threadIdx.x;
    const int v     = blockIdx.x * TPB + tid;
    const int split = blockIdx.y;
    const int b0    = split * BPS;

    if (tid < BPS) slab[tid] = labels[b0 + tid];
#pragma unroll
    for (int c = 0; c < CC; ++c) acc[c][tid] = 0.0f;
    __syncthreads();

    const float* svp = sv + (size_t)b0 * VV + v;
    const float* Wp  = W  + ((size_t)b0 * VV + v) * CC;

    // 8 b's per batch: 16 independent global loads in flight per thread.
#pragma unroll 1
    for (int bb = 0; bb < BPS; bb += 8) {
        int   l[8];
        float s[8];
        float w[8];
#pragma unroll
        for (int k = 0; k < 8; ++k) l[k] = slab[bb + k];
#pragma unroll
        for (int k = 0; k < 8; ++k)
            s[k] = __ldcs(svp + (size_t)(bb + k) * VV);
#pragma unroll
        for (int k = 0; k < 8; ++k)
            w[k] = __ldcs(Wp + (size_t)(bb + k) * VV * CC + l[k]);
#pragma unroll
        for (int k = 0; k < 8; ++k)
            acc[l[k]][tid] += fabsf(s[k] * w[k]);
    }

    // Coalesced partial write (fully written -> no zeroing needed).
    float* outp = g_partial + ((size_t)split * CC) * VV + v;
#pragma unroll
    for (int c = 0; c < CC; ++c)
        outp[(size_t)c * VV] = acc[c][tid];
}

// ---------------------------------------------------------------------------
// Kernel 2: fused count + init-decode + split-reduce + mean + EMA.
// float2 granularity: 262144 threads / 1024 blocks (measured 7.84us,
// occ 68%). Each block's 512 contiguous outputs lie in exactly one class c.
// This exact form produced the best measured total (166.0us, R8). FROZEN.
// ---------------------------------------------------------------------------
__global__ __launch_bounds__(256) void finalize_kernel(
    const float*         __restrict__ centroids,
    const int*           __restrict__ labels,
    const unsigned char* __restrict__ initp,
    float*               __restrict__ out)
{
    const int idx2 = blockIdx.x * blockDim.x + threadIdx.x;   // over C*V/2
    const int idx  = idx2 * 2;
    const int c    = idx >> 15;          // /V  (constant within a block)
    const int v    = idx & (VV - 1);

    __shared__ int s_cnt;
    __shared__ int s_ini;
    if (threadIdx.x == 0) s_cnt = 0;
    __syncthreads();

    // Per-block count of labels == c (2 loads per thread, fully parallel).
    int my = 0;
#pragma unroll
    for (int b = threadIdx.x; b < BB; b += 256)
        my += (labels[b] == c);
    if (my) atomicAdd(&s_cnt, my);

    // Thread 0: decode initialized[c] with dtype sniff (vector loads).
    if (threadIdx.x == 0) {
        const int4  i4 = *(const int4*)initp;          // first 16 bytes
        const unsigned char* bp = (const unsigned char*)&i4;
        bool i32like = true, f32like = true, anyNZ = false;
        for (int i = 0; i < 16; ++i) {
            if ((i & 3) != 0 && bp[i] != 0) i32like = false;
            if (bp[i] != 0) anyNZ = true;
        }
        const float* fp = (const float*)&i4;
        for (int k = 0; k < 4; ++k)
            if (!(fp[k] == 0.0f || fp[k] == 1.0f)) f32like = false;

        int ini;
        if (!anyNZ)       ini = 0;                         // all-zero: representations agree
        else if (f32like) ini = (((const float*)initp)[c] != 0.0f);
        else if (i32like) ini = (((const int*)initp)[c] != 0);
        else              ini = (initp[c] != 0);
        s_ini = ini;
    }
    __syncthreads();

    const int cnt = s_cnt;
    const int ini = s_ini;

    // Deterministic split reduction (fixed order p = 0..7),
    // 8 independent float2 loads issued back-to-back for MLP.
    float2 t[SPLIT];
#pragma unroll
    for (int p = 0; p < SPLIT; ++p)
        t[p] = *(const float2*)&g_partial[((size_t)p * CC + c) * VV + v];

    float2 s = make_float2(0.f, 0.f);
#pragma unroll
    for (int p = 0; p < SPLIT; ++p) { s.x += t[p].x; s.y += t[p].y; }

    const float inv   = 1.0f / fmaxf((float)cnt, 1.0f);
    const float ALPHA = (float)(2.0 / 1001.0);  // 1 - MOMENTUM

    const float2 ct = *(const float2*)&centroids[idx];
    float2 r;
    {
        float m, u;
        m = s.x * inv; u = ini ? (ct.x + ALPHA * (m - ct.x)) : m; r.x = cnt > 0 ? u : ct.x;
        m = s.y * inv; u = ini ? (ct.y + ALPHA * (m - ct.y)) : m; r.y = cnt > 0 ? u : ct.y;
    }
    *(float2*)&out[idx] = r;
}

// ---------------------------------------------------------------------------
// Launch. Inputs bound by UNIQUE element count (robust to metadata order):
//   sparse_vector f32 [B,V]     -> 16,777,216
//   W_eff         f32 [B,V,C]   -> 268,435,456
//   labels        i32 [B]       -> 512
//   centroids     f32 [C,V]     -> 524,288
//   initialized   bool[C]       -> 16
// ---------------------------------------------------------------------------
extern "C" void kernel_launch(void* const* d_in, const int* in_sizes, int n_in,
                              void* d_out, int out_size)
{
    const float*         sv   = nullptr;
    const float*         W    = nullptr;
    const int*           lab  = nullptr;
    const float*         cent = nullptr;
    const unsigned char* init = nullptr;

    for (int i = 0; i < n_in; ++i) {
        long n = (long)in_sizes[i];
        if      (n == (long)BB * VV)       sv   = (const float*)d_in[i];
        else if (n == (long)BB * VV * CC)  W    = (const float*)d_in[i];
        else if (n == (long)BB)            lab  = (const int*)d_in[i];
        else if (n == (long)CC * VV)       cent = (const float*)d_in[i];
        else if (n == (long)CC)            init = (const unsigned char*)d_in[i];
    }
    if (!sv)   sv   = (const float*)d_in[0];
    if (!W)    W    = (const float*)d_in[1];
    if (!lab)  lab  = (const int*)d_in[2];
    if (!cent) cent = (const float*)d_in[3];
    if (!init) init = (const unsigned char*)d_in[4];

    float* out = (float*)d_out;

    accum_kernel<<<dim3(VBLOCKS, SPLIT), TPB>>>(sv, W, lab);
    finalize_kernel<<<(CC * VV / 2) / 256, 256>>>(cent, lab, init, out);
}